// round 8
// baseline (speedup 1.0000x reference)
#include <cuda_runtime.h>
#include <cuda_bf16.h>
#include <cstdint>

#define NN   100000
#define NE   1600000
#define D    128
#define DOUT 64
#define MT   128
#define NBLK ((NN + MT - 1) / MT)     // 782
#define SCANB ((NN + 255) / 256)      // 391

// ---------------- scratch ----------------
__device__ __align__(16) float g_bufA[NN * D];
__device__ __align__(16) float g_bufC[NN * D];
__device__ __align__(16) uint32_t g_hi[NN * (D / 2)];
__device__ __align__(16) uint32_t g_lo[NN * (D / 2)];
__device__ __align__(16) float g_stats2[4 * 256];   // per-stats-GEMM slots: [sum(128), sumsq(128)]
__device__ int g_is64;
__device__ int g_deg[NN];
__device__ int g_off[NN];
__device__ int g_cur[NN];
__device__ int g_csr[NE];
__device__ int g_bsum[512];
__device__ __align__(16) __nv_bfloat16 g_wh[8 * D * D];
__device__ __align__(16) __nv_bfloat16 g_wl[8 * D * D];

__device__ __forceinline__ uint32_t pack2(__nv_bfloat16 a, __nv_bfloat16 b) {
    return (uint32_t)__bfloat16_as_ushort(a) | ((uint32_t)__bfloat16_as_ushort(b) << 16);
}
__device__ __forceinline__ void split2(float x, float y, uint32_t& h, uint32_t& l) {
    __nv_bfloat16 hx = __float2bfloat16(x), hy = __float2bfloat16(y);
    h = pack2(hx, hy);
    l = pack2(__float2bfloat16(x - __bfloat162float(hx)),
              __float2bfloat16(y - __bfloat162float(hy)));
}

#define MMA_BF16(c, a, b0_, b1_) \
    asm volatile("mma.sync.aligned.m16n8k16.row.col.f32.bf16.bf16.f32 " \
        "{%0,%1,%2,%3}, {%4,%5,%6,%7}, {%8,%9}, {%0,%1,%2,%3};" \
        : "+f"((c)[0]), "+f"((c)[1]), "+f"((c)[2]), "+f"((c)[3]) \
        : "r"((a)[0]), "r"((a)[1]), "r"((a)[2]), "r"((a)[3]), "r"(b0_), "r"(b1_))

// ---------------- init: zero deg (+ detect dtype + zero stats in last block) ----------------
__global__ void init_kernel(const void* ei) {
    if (blockIdx.x < SCANB) {
        int i = blockIdx.x * 256 + threadIdx.x;
        if (i < NN) g_deg[i] = 0;
    } else {
        const long long* p = (const long long*)ei;
        long long v = p[threadIdx.x];
        int ok = (v >= 0 && v < NN);
        ok = __syncthreads_and(ok);
        if (threadIdx.x == 0) g_is64 = ok;
        ((float4*)g_stats2)[threadIdx.x] = make_float4(0.f, 0.f, 0.f, 0.f);
    }
}

// transpose + bf16-split all 8 weight matrices: g_wh/g_wl[m][n][k]
__global__ void prep_w(const float* __restrict__ W1, const float* __restrict__ W2,
                       const float* __restrict__ fW1, const float* __restrict__ fW2) {
    int m = blockIdx.y;
    const float* src;
    int ncols;
    if (m < 3)       { src = W1 + m * D * D;       ncols = D; }
    else if (m < 6)  { src = W2 + (m - 3) * D * D; ncols = D; }
    else if (m == 6) { src = fW1;                  ncols = D; }
    else             { src = fW2;                  ncols = DOUT; }
    int idx = blockIdx.x * 256 + threadIdx.x;
    if (idx >= ncols * D) return;
    int n = idx / D, k = idx % D;
    float v = __ldg(src + k * ncols + n);
    __nv_bfloat16 h = __float2bfloat16(v);
    g_wh[m * D * D + idx] = h;
    g_wl[m * D * D + idx] = __float2bfloat16(v - __bfloat162float(h));
}

__global__ void hist_kernel(const void* ei) {
    int e = blockIdx.x * 256 + threadIdx.x;
    if (e >= NE) return;
    int d = g_is64 ? (int)((const long long*)ei)[NE + e] : ((const int*)ei)[NE + e];
    atomicAdd(&g_deg[d], 1);
}
__global__ void scan1_kernel() {
    __shared__ int s[256];
    int i = blockIdx.x * 256 + threadIdx.x;
    int v = (i < NN) ? g_deg[i] : 0;
    s[threadIdx.x] = v;
    __syncthreads();
    for (int o = 1; o < 256; o <<= 1) {
        int t = (threadIdx.x >= o) ? s[threadIdx.x - o] : 0;
        __syncthreads();
        s[threadIdx.x] += t;
        __syncthreads();
    }
    if (i < NN) g_off[i] = s[threadIdx.x];
    if (threadIdx.x == 255) g_bsum[blockIdx.x] = s[255];
}
__global__ void scan2_kernel() {
    __shared__ int s[512];
    int v = (threadIdx.x < SCANB) ? g_bsum[threadIdx.x] : 0;
    s[threadIdx.x] = v;
    __syncthreads();
    for (int o = 1; o < 512; o <<= 1) {
        int t = (threadIdx.x >= o) ? s[threadIdx.x - o] : 0;
        __syncthreads();
        s[threadIdx.x] += t;
        __syncthreads();
    }
    g_bsum[threadIdx.x] = s[threadIdx.x] - v;
}
__global__ void scan3_kernel() {
    int i = blockIdx.x * 256 + threadIdx.x;
    if (i >= NN) return;
    int e = g_off[i] - g_deg[i] + g_bsum[blockIdx.x];
    g_off[i] = e;
    g_cur[i] = e;
}
__global__ void fill_kernel(const void* ei) {
    int e = blockIdx.x * 256 + threadIdx.x;
    if (e >= NE) return;
    int s, d;
    if (g_is64) { const long long* p = (const long long*)ei; s = (int)p[e]; d = (int)p[NE + e]; }
    else        { const int* p = (const int*)ei;             s = p[e];      d = p[NE + e]; }
    int pos = atomicAdd(&g_cur[d], 1);
    g_csr[pos] = s;
}

// gather h[w] = x[w] + sum_j x[csr[j]]  -> bf16 hi/lo split, one warp per node
__global__ __launch_bounds__(256)
void gather_bf16_kernel(const float* __restrict__ x,
                        uint32_t* __restrict__ hi, uint32_t* __restrict__ lo) {
    int w = (blockIdx.x * 256 + threadIdx.x) >> 5;
    int lane = threadIdx.x & 31;
    if (w >= NN) return;
    const float4* xb = (const float4*)x;
    float4 acc = __ldg(xb + (size_t)w * 32 + lane);
    int i = g_off[w];
    int end = i + g_deg[w];
    for (; i + 8 <= end; i += 8) {
        int s0 = __ldg(g_csr + i),     s1 = __ldg(g_csr + i + 1);
        int s2 = __ldg(g_csr + i + 2), s3 = __ldg(g_csr + i + 3);
        int s4 = __ldg(g_csr + i + 4), s5 = __ldg(g_csr + i + 5);
        int s6 = __ldg(g_csr + i + 6), s7 = __ldg(g_csr + i + 7);
        float4 v0 = __ldg(xb + (size_t)s0 * 32 + lane);
        float4 v1 = __ldg(xb + (size_t)s1 * 32 + lane);
        float4 v2 = __ldg(xb + (size_t)s2 * 32 + lane);
        float4 v3 = __ldg(xb + (size_t)s3 * 32 + lane);
        float4 v4 = __ldg(xb + (size_t)s4 * 32 + lane);
        float4 v5 = __ldg(xb + (size_t)s5 * 32 + lane);
        float4 v6 = __ldg(xb + (size_t)s6 * 32 + lane);
        float4 v7 = __ldg(xb + (size_t)s7 * 32 + lane);
        acc.x += ((v0.x + v1.x) + (v2.x + v3.x)) + ((v4.x + v5.x) + (v6.x + v7.x));
        acc.y += ((v0.y + v1.y) + (v2.y + v3.y)) + ((v4.y + v5.y) + (v6.y + v7.y));
        acc.z += ((v0.z + v1.z) + (v2.z + v3.z)) + ((v4.z + v5.z) + (v6.z + v7.z));
        acc.w += ((v0.w + v1.w) + (v2.w + v3.w)) + ((v4.w + v5.w) + (v6.w + v7.w));
    }
    for (; i + 2 <= end; i += 2) {
        int s0 = __ldg(g_csr + i), s1 = __ldg(g_csr + i + 1);
        float4 v0 = __ldg(xb + (size_t)s0 * 32 + lane);
        float4 v1 = __ldg(xb + (size_t)s1 * 32 + lane);
        acc.x += v0.x + v1.x; acc.y += v0.y + v1.y;
        acc.z += v0.z + v1.z; acc.w += v0.w + v1.w;
    }
    if (i < end) {
        int s = __ldg(g_csr + i);
        float4 v = __ldg(xb + (size_t)s * 32 + lane);
        acc.x += v.x; acc.y += v.y; acc.z += v.z; acc.w += v.w;
    }
    uint32_t h0, l0, h1, l1;
    split2(acc.x, acc.y, h0, l0);
    split2(acc.z, acc.w, h1, l1);
    ((uint2*)hi)[(size_t)w * 32 + lane] = make_uint2(h0, h1);
    ((uint2*)lo)[(size_t)w * 32 + lane] = make_uint2(l0, l1);
}

// convert fp32 -> bf16 hi/lo; BN variant computes scale/shift inline from raw sums
template <bool BN>
__global__ __launch_bounds__(256)
void conv_split_kernel(const float* __restrict__ C,
                       uint32_t* __restrict__ hi, uint32_t* __restrict__ lo,
                       const float* __restrict__ stats,
                       const float* __restrict__ gamma, const float* __restrict__ beta) {
    int i0 = (blockIdx.x * 256 + threadIdx.x) * 2;
    if (i0 >= NN * 32) return;
    float4 sc, sh;
    if (BN) {
        int k = (i0 & 31) * 4;   // i0 even -> both float4s share the same 8-col window? no:
        // i0 and i0+1 cover cols k..k+7
        float4 s0 = *(const float4*)(stats + k);
        float4 s1 = *(const float4*)(stats + k + 4);
        float4 q0 = *(const float4*)(stats + 128 + k);
        float4 q1 = *(const float4*)(stats + 128 + k + 4);
        float4 ga0 = __ldg((const float4*)(gamma + k));
        float4 ga1 = __ldg((const float4*)(gamma + k + 4));
        float4 be0 = __ldg((const float4*)(beta + k));
        float4 be1 = __ldg((const float4*)(beta + k + 4));
        const float inv = 1.0f / NN;
        float mu;
        mu = s0.x * inv; sc.x = ga0.x * rsqrtf(q0.x * inv - mu * mu + 1e-5f); sh.x = be0.x - mu * sc.x;
        mu = s0.y * inv; sc.y = ga0.y * rsqrtf(q0.y * inv - mu * mu + 1e-5f); sh.y = be0.y - mu * sc.y;
        mu = s0.z * inv; sc.z = ga0.z * rsqrtf(q0.z * inv - mu * mu + 1e-5f); sh.z = be0.z - mu * sc.z;
        mu = s0.w * inv; sc.w = ga0.w * rsqrtf(q0.w * inv - mu * mu + 1e-5f); sh.w = be0.w - mu * sc.w;
        // second half
        float4 sc2, sh2;
        mu = s1.x * inv; sc2.x = ga1.x * rsqrtf(q1.x * inv - mu * mu + 1e-5f); sh2.x = be1.x - mu * sc2.x;
        mu = s1.y * inv; sc2.y = ga1.y * rsqrtf(q1.y * inv - mu * mu + 1e-5f); sh2.y = be1.y - mu * sc2.y;
        mu = s1.z * inv; sc2.z = ga1.z * rsqrtf(q1.z * inv - mu * mu + 1e-5f); sh2.z = be1.z - mu * sc2.z;
        mu = s1.w * inv; sc2.w = ga1.w * rsqrtf(q1.w * inv - mu * mu + 1e-5f); sh2.w = be1.w - mu * sc2.w;

        float4 v0 = __ldg((const float4*)C + i0);
        float4 v1 = __ldg((const float4*)C + i0 + 1);
        v0.x = fmaxf(fmaf(v0.x, sc.x, sh.x), 0.f);
        v0.y = fmaxf(fmaf(v0.y, sc.y, sh.y), 0.f);
        v0.z = fmaxf(fmaf(v0.z, sc.z, sh.z), 0.f);
        v0.w = fmaxf(fmaf(v0.w, sc.w, sh.w), 0.f);
        v1.x = fmaxf(fmaf(v1.x, sc2.x, sh2.x), 0.f);
        v1.y = fmaxf(fmaf(v1.y, sc2.y, sh2.y), 0.f);
        v1.z = fmaxf(fmaf(v1.z, sc2.z, sh2.z), 0.f);
        v1.w = fmaxf(fmaf(v1.w, sc2.w, sh2.w), 0.f);
        uint32_t h0, l0v, h1, l1;
        split2(v0.x, v0.y, h0, l0v);
        split2(v0.z, v0.w, h1, l1);
        ((uint2*)hi)[i0] = make_uint2(h0, h1);
        ((uint2*)lo)[i0] = make_uint2(l0v, l1);
        split2(v1.x, v1.y, h0, l0v);
        split2(v1.z, v1.w, h1, l1);
        ((uint2*)hi)[i0 + 1] = make_uint2(h0, h1);
        ((uint2*)lo)[i0 + 1] = make_uint2(l0v, l1);
    } else {
        float4 v0 = __ldg((const float4*)C + i0);
        float4 v1 = __ldg((const float4*)C + i0 + 1);
        uint32_t h0, l0v, h1, l1;
        split2(v0.x, v0.y, h0, l0v);
        split2(v0.z, v0.w, h1, l1);
        ((uint2*)hi)[i0] = make_uint2(h0, h1);
        ((uint2*)lo)[i0] = make_uint2(l0v, l1);
        split2(v1.x, v1.y, h0, l0v);
        split2(v1.z, v1.w, h1, l1);
        ((uint2*)hi)[i0 + 1] = make_uint2(h0, h1);
        ((uint2*)lo)[i0 + 1] = make_uint2(l0v, l1);
    }
}

// ---------------- HMMA GEMM: Out[M,NOUT] = split(A) @ Wt^T + bias ----------------
// STATS: fused column sum/sumsq of Out into stats[0:256) (shfl-reduced epilogue).
template <int NOUT, bool RELU, bool STATS>
__global__ __launch_bounds__(256, 2)
void mma_gemm(const uint32_t* __restrict__ Ahi, const uint32_t* __restrict__ Alo,
              const uint32_t* __restrict__ Wh, const uint32_t* __restrict__ Wl,
              const float* __restrict__ bias, float* __restrict__ Out,
              float* __restrict__ stats) {
    constexpr int WM = (NOUT == 128) ? 4 : 8;   // warps along m
    constexpr int MF = 128 / (WM * 16);         // m16 frags per warp
    constexpr int RS = 68;                      // smem row stride (u32), pad for banks
    extern __shared__ uint32_t ws[];
    uint32_t* wh_s = ws;
    uint32_t* wl_s = ws + NOUT * RS;
    __shared__ float ssum[128], ssq[128];

    int tid = threadIdx.x;
    for (int i = tid; i < NOUT * 64; i += 256) {
        int n = i >> 6, kw = i & 63;
        wh_s[n * RS + kw] = __ldg(Wh + i);
        wl_s[n * RS + kw] = __ldg(Wl + i);
    }
    if (STATS && tid < 128) { ssum[tid] = 0.f; ssq[tid] = 0.f; }
    __syncthreads();

    int wid = tid >> 5, lane = tid & 31;
    int g = lane >> 2, tig = lane & 3;
    int mwid = wid % WM, nwid = wid / WM;
    int n0 = nwid * 64;
    int mbase = blockIdx.x * MT + mwid * (MF * 16);

    float acc[MF][8][4];
#pragma unroll
    for (int mf = 0; mf < MF; ++mf)
#pragma unroll
        for (int nf = 0; nf < 8; ++nf)
#pragma unroll
            for (int c = 0; c < 4; ++c) acc[mf][nf][c] = 0.f;

    for (int ks = 0; ks < 8; ++ks) {
        uint32_t ah[MF][4], al[MF][4];
#pragma unroll
        for (int mf = 0; mf < MF; ++mf) {
            int r0 = mbase + mf * 16 + g;
            int r1 = r0 + 8;
            int o = ks * 8 + tig;
            bool v0 = r0 < NN, v1 = r1 < NN;
            size_t p0 = (size_t)r0 * 64 + o, p1 = (size_t)r1 * 64 + o;
            ah[mf][0] = v0 ? __ldg(Ahi + p0) : 0u;
            ah[mf][1] = v1 ? __ldg(Ahi + p1) : 0u;
            ah[mf][2] = v0 ? __ldg(Ahi + p0 + 4) : 0u;
            ah[mf][3] = v1 ? __ldg(Ahi + p1 + 4) : 0u;
            al[mf][0] = v0 ? __ldg(Alo + p0) : 0u;
            al[mf][1] = v1 ? __ldg(Alo + p1) : 0u;
            al[mf][2] = v0 ? __ldg(Alo + p0 + 4) : 0u;
            al[mf][3] = v1 ? __ldg(Alo + p1 + 4) : 0u;
        }
#pragma unroll
        for (int nf = 0; nf < 8; ++nf) {
            int bo = (n0 + nf * 8 + g) * RS + ks * 8 + tig;
            uint32_t bh0 = wh_s[bo], bh1 = wh_s[bo + 4];
            uint32_t bl0 = wl_s[bo], bl1 = wl_s[bo + 4];
#pragma unroll
            for (int mf = 0; mf < MF; ++mf) {
                MMA_BF16(acc[mf][nf], ah[mf], bh0, bh1);
                MMA_BF16(acc[mf][nf], al[mf], bh0, bh1);
                MMA_BF16(acc[mf][nf], ah[mf], bl0, bl1);
            }
        }
    }

#pragma unroll
    for (int nf = 0; nf < 8; ++nf) {
        int col = n0 + nf * 8 + tig * 2;
        float2 b = *(const float2*)(bias + col);
        float s0 = 0.f, s1 = 0.f, q0 = 0.f, q1 = 0.f;
#pragma unroll
        for (int mf = 0; mf < MF; ++mf) {
            int r0 = mbase + mf * 16 + g;
            int r1 = r0 + 8;
            float c0 = acc[mf][nf][0] + b.x, c1 = acc[mf][nf][1] + b.y;
            float c2 = acc[mf][nf][2] + b.x, c3 = acc[mf][nf][3] + b.y;
            if (RELU) {
                c0 = fmaxf(c0, 0.f); c1 = fmaxf(c1, 0.f);
                c2 = fmaxf(c2, 0.f); c3 = fmaxf(c3, 0.f);
            }
            if (r0 < NN) {
                *(float2*)(Out + (size_t)r0 * NOUT + col) = make_float2(c0, c1);
                if (STATS) { s0 += c0; s1 += c1; q0 += c0 * c0; q1 += c1 * c1; }
            }
            if (r1 < NN) {
                *(float2*)(Out + (size_t)r1 * NOUT + col) = make_float2(c2, c3);
                if (STATS) { s0 += c2; s1 += c3; q0 += c2 * c2; q1 += c3 * c3; }
            }
        }
        if (STATS) {
#pragma unroll
            for (int o = 4; o < 32; o <<= 1) {
                s0 += __shfl_xor_sync(0xFFFFFFFFu, s0, o);
                s1 += __shfl_xor_sync(0xFFFFFFFFu, s1, o);
                q0 += __shfl_xor_sync(0xFFFFFFFFu, q0, o);
                q1 += __shfl_xor_sync(0xFFFFFFFFu, q1, o);
            }
            if (lane < 4) {
                atomicAdd(&ssum[col], s0);
                atomicAdd(&ssum[col + 1], s1);
                atomicAdd(&ssq[col], q0);
                atomicAdd(&ssq[col + 1], q1);
            }
        }
    }
    if (STATS) {
        __syncthreads();
        if (tid < 128) {
            atomicAdd(&stats[tid], ssum[tid]);
            atomicAdd(&stats[128 + tid], ssq[tid]);
        }
    }
}

// ---------------- host ----------------
extern "C" void kernel_launch(void* const* d_in, const int* in_sizes, int n_in,
                              void* d_out, int out_size) {
    const float* x    = (const float*)d_in[0];
    const void*  ei   = d_in[1];
    const float* W1   = (const float*)d_in[2];
    const float* b1   = (const float*)d_in[3];
    const float* g1   = (const float*)d_in[4];
    const float* be1  = (const float*)d_in[5];
    const float* W2   = (const float*)d_in[6];
    const float* b2   = (const float*)d_in[7];
    const float* fW1  = (const float*)d_in[8];
    const float* fb1  = (const float*)d_in[9];
    const float* fg1  = (const float*)d_in[10];
    const float* fbe1 = (const float*)d_in[11];
    const float* fW2  = (const float*)d_in[12];
    const float* fb2  = (const float*)d_in[13];
    float* out = (float*)d_out;

    float *A, *C, *st;
    uint32_t *hi, *lo, *wh, *wl;
    cudaGetSymbolAddress((void**)&A, g_bufA);
    cudaGetSymbolAddress((void**)&C, g_bufC);
    cudaGetSymbolAddress((void**)&st, g_stats2);
    cudaGetSymbolAddress((void**)&hi, g_hi);
    cudaGetSymbolAddress((void**)&lo, g_lo);
    cudaGetSymbolAddress((void**)&wh, g_wh);
    cudaGetSymbolAddress((void**)&wl, g_wl);

    const int SMA = 128 * 68 * 4 * 2;   // 69632 B
    const int SMB = 64 * 68 * 4 * 2;    // 34816 B
    cudaFuncSetAttribute(mma_gemm<128, false, true>,
                         cudaFuncAttributeMaxDynamicSharedMemorySize, SMA);
    cudaFuncSetAttribute(mma_gemm<128, true, false>,
                         cudaFuncAttributeMaxDynamicSharedMemorySize, SMA);
    cudaFuncSetAttribute(mma_gemm<64, false, false>,
                         cudaFuncAttributeMaxDynamicSharedMemorySize, SMB);

    init_kernel<<<SCANB + 1, 256>>>(ei);
    prep_w<<<dim3(64, 8), 256>>>(W1, W2, fW1, fW2);
    hist_kernel<<<NE / 256, 256>>>(ei);
    scan1_kernel<<<SCANB, 256>>>();
    scan2_kernel<<<1, 512>>>();
    scan3_kernel<<<SCANB, 256>>>();
    fill_kernel<<<NE / 256, 256>>>(ei);

    const int gblocks = (NN * 32 + 255) / 256;       // 12500
    const int cblocks = (NN * 16 + 255) / 256;       // 6250

    const float* cur = x;
    for (int l = 0; l < 3; ++l) {
        gather_bf16_kernel<<<gblocks, 256>>>(cur, hi, lo);
        mma_gemm<128, false, true><<<NBLK, 256, SMA>>>(
            hi, lo, wh + (size_t)l * D * 64, wl + (size_t)l * D * 64, b1 + l * D, C,
            st + l * 256);
        conv_split_kernel<true><<<cblocks, 256>>>(C, hi, lo, st + l * 256,
                                                  g1 + l * D, be1 + l * D);
        mma_gemm<128, true, false><<<NBLK, 256, SMA>>>(
            hi, lo, wh + (size_t)(3 + l) * D * 64, wl + (size_t)(3 + l) * D * 64, b2 + l * D, A,
            nullptr);
        cur = A;
    }
    // final MLP
    conv_split_kernel<false><<<cblocks, 256>>>(cur, hi, lo, nullptr, nullptr, nullptr);
    mma_gemm<128, false, true><<<NBLK, 256, SMA>>>(
        hi, lo, wh + (size_t)6 * D * 64, wl + (size_t)6 * D * 64, fb1, C, st + 3 * 256);
    conv_split_kernel<true><<<cblocks, 256>>>(C, hi, lo, st + 3 * 256, fg1, fbe1);
    mma_gemm<64, false, false><<<NBLK, 256, SMB>>>(
        hi, lo, wh + (size_t)7 * D * 64, wl + (size_t)7 * D * 64, fb2, out, nullptr);
}

// round 9
// speedup vs baseline: 1.0589x; 1.0589x over previous
#include <cuda_runtime.h>
#include <cuda_bf16.h>
#include <cstdint>

#define NN   100000
#define NE   1600000
#define D    128
#define DOUT 64
#define MT   128
#define NBLK ((NN + MT - 1) / MT)     // 782
#define SCANB ((NN + 255) / 256)      // 391

// ---------------- scratch ----------------
__device__ __align__(16) float g_bufA[NN * D];
__device__ __align__(16) float g_bufC[NN * D];
__device__ __align__(16) uint32_t g_hi[NN * (D / 2)];
__device__ __align__(16) uint32_t g_lo[NN * (D / 2)];
__device__ __align__(16) float g_stats[512];   // [0:128) sum, [128:256) sumsq, [256:384) scale, [384:512) shift
__device__ int g_is64;
__device__ int g_deg[NN];
__device__ int g_off[NN];
__device__ int g_cur[NN];
__device__ int g_csr[NE];
__device__ int g_bsum[512];
__device__ __align__(16) __nv_bfloat16 g_wh[8 * D * D];
__device__ __align__(16) __nv_bfloat16 g_wl[8 * D * D];

__device__ __forceinline__ uint32_t pack2(__nv_bfloat16 a, __nv_bfloat16 b) {
    return (uint32_t)__bfloat16_as_ushort(a) | ((uint32_t)__bfloat16_as_ushort(b) << 16);
}
__device__ __forceinline__ void split2(float x, float y, uint32_t& h, uint32_t& l) {
    __nv_bfloat16 hx = __float2bfloat16(x), hy = __float2bfloat16(y);
    h = pack2(hx, hy);
    l = pack2(__float2bfloat16(x - __bfloat162float(hx)),
              __float2bfloat16(y - __bfloat162float(hy)));
}

#define MMA_BF16(c, a, b0_, b1_) \
    asm volatile("mma.sync.aligned.m16n8k16.row.col.f32.bf16.bf16.f32 " \
        "{%0,%1,%2,%3}, {%4,%5,%6,%7}, {%8,%9}, {%0,%1,%2,%3};" \
        : "+f"((c)[0]), "+f"((c)[1]), "+f"((c)[2]), "+f"((c)[3]) \
        : "r"((a)[0]), "r"((a)[1]), "r"((a)[2]), "r"((a)[3]), "r"(b0_), "r"(b1_))

// ---------------- small kernels ----------------
__global__ void detect_kernel(const void* ei) {
    const long long* p = (const long long*)ei;
    long long v = p[threadIdx.x];
    int ok = (v >= 0 && v < NN);
    ok = __syncthreads_and(ok);
    if (threadIdx.x == 0) g_is64 = ok;
}

// transpose + bf16-split all 8 weight matrices: g_wh/g_wl[m][n][k]
__global__ void prep_w(const float* __restrict__ W1, const float* __restrict__ W2,
                       const float* __restrict__ fW1, const float* __restrict__ fW2) {
    int m = blockIdx.y;
    const float* src;
    int ncols;
    if (m < 3)       { src = W1 + m * D * D;       ncols = D; }
    else if (m < 6)  { src = W2 + (m - 3) * D * D; ncols = D; }
    else if (m == 6) { src = fW1;                  ncols = D; }
    else             { src = fW2;                  ncols = DOUT; }
    int idx = blockIdx.x * 256 + threadIdx.x;
    if (idx >= ncols * D) return;
    int n = idx / D, k = idx % D;
    float v = __ldg(src + k * ncols + n);
    __nv_bfloat16 h = __float2bfloat16(v);
    g_wh[m * D * D + idx] = h;
    g_wl[m * D * D + idx] = __float2bfloat16(v - __bfloat162float(h));
}

__global__ void zero_deg_kernel() {
    int i = blockIdx.x * 256 + threadIdx.x;
    if (i < NN) g_deg[i] = 0;
}
__global__ void hist_kernel(const void* ei) {
    int e = blockIdx.x * 256 + threadIdx.x;
    if (e >= NE) return;
    int d = g_is64 ? (int)((const long long*)ei)[NE + e] : ((const int*)ei)[NE + e];
    atomicAdd(&g_deg[d], 1);
}
__global__ void scan1_kernel() {
    __shared__ int s[256];
    int i = blockIdx.x * 256 + threadIdx.x;
    int v = (i < NN) ? g_deg[i] : 0;
    s[threadIdx.x] = v;
    __syncthreads();
    for (int o = 1; o < 256; o <<= 1) {
        int t = (threadIdx.x >= o) ? s[threadIdx.x - o] : 0;
        __syncthreads();
        s[threadIdx.x] += t;
        __syncthreads();
    }
    if (i < NN) g_off[i] = s[threadIdx.x];
    if (threadIdx.x == 255) g_bsum[blockIdx.x] = s[255];
}
__global__ void scan2_kernel() {
    __shared__ int s[512];
    int v = (threadIdx.x < SCANB) ? g_bsum[threadIdx.x] : 0;
    s[threadIdx.x] = v;
    __syncthreads();
    for (int o = 1; o < 512; o <<= 1) {
        int t = (threadIdx.x >= o) ? s[threadIdx.x - o] : 0;
        __syncthreads();
        s[threadIdx.x] += t;
        __syncthreads();
    }
    g_bsum[threadIdx.x] = s[threadIdx.x] - v;
}
__global__ void scan3_kernel() {
    int i = blockIdx.x * 256 + threadIdx.x;
    if (i >= NN) return;
    int e = g_off[i] - g_deg[i] + g_bsum[blockIdx.x];
    g_off[i] = e;
    g_cur[i] = e;
}
__global__ void fill_kernel(const void* ei) {
    int e = blockIdx.x * 256 + threadIdx.x;
    if (e >= NE) return;
    int s, d;
    if (g_is64) { const long long* p = (const long long*)ei; s = (int)p[e]; d = (int)p[NE + e]; }
    else        { const int* p = (const int*)ei;             s = p[e];      d = p[NE + e]; }
    int pos = atomicAdd(&g_cur[d], 1);
    g_csr[pos] = s;
}

// gather h[w] = x[w] + sum_j x[csr[j]]  -> bf16 hi/lo split, one warp per node
__global__ __launch_bounds__(256)
void gather_bf16_kernel(const float* __restrict__ x,
                        uint32_t* __restrict__ hi, uint32_t* __restrict__ lo) {
    int w = (blockIdx.x * 256 + threadIdx.x) >> 5;
    int lane = threadIdx.x & 31;
    if (w >= NN) return;
    const float4* xb = (const float4*)x;
    float4 acc = __ldg(xb + (size_t)w * 32 + lane);
    int i = g_off[w];
    int end = i + g_deg[w];
    for (; i + 4 <= end; i += 4) {
        int s0 = __ldg(g_csr + i),     s1 = __ldg(g_csr + i + 1);
        int s2 = __ldg(g_csr + i + 2), s3 = __ldg(g_csr + i + 3);
        float4 v0 = __ldg(xb + (size_t)s0 * 32 + lane);
        float4 v1 = __ldg(xb + (size_t)s1 * 32 + lane);
        float4 v2 = __ldg(xb + (size_t)s2 * 32 + lane);
        float4 v3 = __ldg(xb + (size_t)s3 * 32 + lane);
        acc.x += (v0.x + v1.x) + (v2.x + v3.x);
        acc.y += (v0.y + v1.y) + (v2.y + v3.y);
        acc.z += (v0.z + v1.z) + (v2.z + v3.z);
        acc.w += (v0.w + v1.w) + (v2.w + v3.w);
    }
    for (; i < end; ++i) {
        int s = __ldg(g_csr + i);
        float4 v = __ldg(xb + (size_t)s * 32 + lane);
        acc.x += v.x; acc.y += v.y; acc.z += v.z; acc.w += v.w;
    }
    uint32_t h0, l0, h1, l1;
    split2(acc.x, acc.y, h0, l0);
    split2(acc.z, acc.w, h1, l1);
    ((uint2*)hi)[(size_t)w * 32 + lane] = make_uint2(h0, h1);
    ((uint2*)lo)[(size_t)w * 32 + lane] = make_uint2(l0, l1);
}

__global__ void zero_stats_kernel() {
    if (threadIdx.x < 256) g_stats[threadIdx.x] = 0.f;
}
// compute scale/shift, then re-zero accumulators for the next stats GEMM
__global__ void finalize_stats_kernel(const float* __restrict__ gamma,
                                      const float* __restrict__ beta) {
    int n = threadIdx.x;
    float mu  = g_stats[n] * (1.0f / NN);
    float var = g_stats[128 + n] * (1.0f / NN) - mu * mu;
    float sc  = __ldg(gamma + n) * rsqrtf(var + 1e-5f);
    g_stats[256 + n] = sc;
    g_stats[384 + n] = __ldg(beta + n) - mu * sc;
    g_stats[n] = 0.f;
    g_stats[128 + n] = 0.f;
}

// convert fp32 -> bf16 hi/lo, applying BN(scale/shift)+ReLU
__global__ __launch_bounds__(256)
void conv_split_bn_kernel(const float* __restrict__ C,
                          uint32_t* __restrict__ hi, uint32_t* __restrict__ lo) {
    int i = blockIdx.x * 256 + threadIdx.x;
    if (i >= NN * 32) return;
    float4 v = __ldg((const float4*)C + i);
    int k = (i & 31) * 4;
    float4 sc = *(const float4*)(g_stats + 256 + k);
    float4 sh = *(const float4*)(g_stats + 384 + k);
    v.x = fmaxf(fmaf(v.x, sc.x, sh.x), 0.f);
    v.y = fmaxf(fmaf(v.y, sc.y, sh.y), 0.f);
    v.z = fmaxf(fmaf(v.z, sc.z, sh.z), 0.f);
    v.w = fmaxf(fmaf(v.w, sc.w, sh.w), 0.f);
    uint32_t h0, l0, h1, l1;
    split2(v.x, v.y, h0, l0);
    split2(v.z, v.w, h1, l1);
    ((uint2*)hi)[i] = make_uint2(h0, h1);
    ((uint2*)lo)[i] = make_uint2(l0, l1);
}

// ---------------- HMMA GEMM: Out = split(A) @ Wt^T + bias ----------------
// A hi/lo: [NN,128] bf16 packed as u32 pairs. Wt hi/lo: [NOUT,128] bf16 (n-major).
// STATS: fused column sum/sumsq of Out into g_stats[0:256) (shfl-reduced epilogue).
// EMIT:  0 = store fp32 Out; 1 = store bf16 hi/lo split (Ohi/Olo) instead.
template <int NOUT, bool RELU, bool STATS, int EMIT>
__global__ __launch_bounds__(256, 2)
void mma_gemm(const uint32_t* __restrict__ Ahi, const uint32_t* __restrict__ Alo,
              const uint32_t* __restrict__ Wh, const uint32_t* __restrict__ Wl,
              const float* __restrict__ bias, float* __restrict__ Out,
              uint32_t* __restrict__ Ohi, uint32_t* __restrict__ Olo) {
    constexpr int WM = (NOUT == 128) ? 4 : 8;   // warps along m
    constexpr int MF = 128 / (WM * 16);         // m16 frags per warp
    constexpr int RS = 68;                      // smem row stride (u32), pad for banks
    extern __shared__ uint32_t ws[];
    uint32_t* wh_s = ws;
    uint32_t* wl_s = ws + NOUT * RS;
    __shared__ float ssum[128], ssq[128];

    int tid = threadIdx.x;
    for (int i = tid; i < NOUT * 64; i += 256) {
        int n = i >> 6, kw = i & 63;
        wh_s[n * RS + kw] = __ldg(Wh + i);
        wl_s[n * RS + kw] = __ldg(Wl + i);
    }
    if (STATS && tid < 128) { ssum[tid] = 0.f; ssq[tid] = 0.f; }
    __syncthreads();

    int wid = tid >> 5, lane = tid & 31;
    int g = lane >> 2, tig = lane & 3;
    int mwid = wid % WM, nwid = wid / WM;
    int n0 = nwid * 64;
    int mbase = blockIdx.x * MT + mwid * (MF * 16);

    float acc[MF][8][4];
#pragma unroll
    for (int mf = 0; mf < MF; ++mf)
#pragma unroll
        for (int nf = 0; nf < 8; ++nf)
#pragma unroll
            for (int c = 0; c < 4; ++c) acc[mf][nf][c] = 0.f;

    for (int ks = 0; ks < 8; ++ks) {
        uint32_t ah[MF][4], al[MF][4];
#pragma unroll
        for (int mf = 0; mf < MF; ++mf) {
            int r0 = mbase + mf * 16 + g;
            int r1 = r0 + 8;
            int o = ks * 8 + tig;
            bool v0 = r0 < NN, v1 = r1 < NN;
            size_t p0 = (size_t)r0 * 64 + o, p1 = (size_t)r1 * 64 + o;
            ah[mf][0] = v0 ? __ldg(Ahi + p0) : 0u;
            ah[mf][1] = v1 ? __ldg(Ahi + p1) : 0u;
            ah[mf][2] = v0 ? __ldg(Ahi + p0 + 4) : 0u;
            ah[mf][3] = v1 ? __ldg(Ahi + p1 + 4) : 0u;
            al[mf][0] = v0 ? __ldg(Alo + p0) : 0u;
            al[mf][1] = v1 ? __ldg(Alo + p1) : 0u;
            al[mf][2] = v0 ? __ldg(Alo + p0 + 4) : 0u;
            al[mf][3] = v1 ? __ldg(Alo + p1 + 4) : 0u;
        }
#pragma unroll
        for (int nf = 0; nf < 8; ++nf) {
            int bo = (n0 + nf * 8 + g) * RS + ks * 8 + tig;
            uint32_t bh0 = wh_s[bo], bh1 = wh_s[bo + 4];
            uint32_t bl0 = wl_s[bo], bl1 = wl_s[bo + 4];
#pragma unroll
            for (int mf = 0; mf < MF; ++mf) {
                MMA_BF16(acc[mf][nf], ah[mf], bh0, bh1);
                MMA_BF16(acc[mf][nf], al[mf], bh0, bh1);
                MMA_BF16(acc[mf][nf], ah[mf], bl0, bl1);
            }
        }
    }

#pragma unroll
    for (int nf = 0; nf < 8; ++nf) {
        int col = n0 + nf * 8 + tig * 2;
        float2 b = *(const float2*)(bias + col);
        float s0 = 0.f, s1 = 0.f, q0 = 0.f, q1 = 0.f;
#pragma unroll
        for (int mf = 0; mf < MF; ++mf) {
            int r0 = mbase + mf * 16 + g;
            int r1 = r0 + 8;
            float c0 = acc[mf][nf][0] + b.x, c1 = acc[mf][nf][1] + b.y;
            float c2 = acc[mf][nf][2] + b.x, c3 = acc[mf][nf][3] + b.y;
            if (RELU) {
                c0 = fmaxf(c0, 0.f); c1 = fmaxf(c1, 0.f);
                c2 = fmaxf(c2, 0.f); c3 = fmaxf(c3, 0.f);
            }
            if (r0 < NN) {
                if (EMIT) {
                    uint32_t hh, ll;
                    split2(c0, c1, hh, ll);
                    Ohi[(size_t)r0 * 64 + col / 2] = hh;
                    Olo[(size_t)r0 * 64 + col / 2] = ll;
                } else {
                    *(float2*)(Out + (size_t)r0 * NOUT + col) = make_float2(c0, c1);
                }
                if (STATS) { s0 += c0; s1 += c1; q0 += c0 * c0; q1 += c1 * c1; }
            }
            if (r1 < NN) {
                if (EMIT) {
                    uint32_t hh, ll;
                    split2(c2, c3, hh, ll);
                    Ohi[(size_t)r1 * 64 + col / 2] = hh;
                    Olo[(size_t)r1 * 64 + col / 2] = ll;
                } else {
                    *(float2*)(Out + (size_t)r1 * NOUT + col) = make_float2(c2, c3);
                }
                if (STATS) { s0 += c2; s1 += c3; q0 += c2 * c2; q1 += c3 * c3; }
            }
        }
        if (STATS) {
            // lanes with same (tig,nf) differ only in g (stride-4 lanes): butterfly them
#pragma unroll
            for (int o = 4; o < 32; o <<= 1) {
                s0 += __shfl_xor_sync(0xFFFFFFFFu, s0, o);
                s1 += __shfl_xor_sync(0xFFFFFFFFu, s1, o);
                q0 += __shfl_xor_sync(0xFFFFFFFFu, q0, o);
                q1 += __shfl_xor_sync(0xFFFFFFFFu, q1, o);
            }
            if (lane < 4) {
                atomicAdd(&ssum[col], s0);
                atomicAdd(&ssum[col + 1], s1);
                atomicAdd(&ssq[col], q0);
                atomicAdd(&ssq[col + 1], q1);
            }
        }
    }
    if (STATS) {
        __syncthreads();
        if (tid < 128) {
            atomicAdd(&g_stats[tid], ssum[tid]);
            atomicAdd(&g_stats[128 + tid], ssq[tid]);
        }
    }
}

// ---------------- host ----------------
extern "C" void kernel_launch(void* const* d_in, const int* in_sizes, int n_in,
                              void* d_out, int out_size) {
    const float* x    = (const float*)d_in[0];
    const void*  ei   = d_in[1];
    const float* W1   = (const float*)d_in[2];
    const float* b1   = (const float*)d_in[3];
    const float* g1   = (const float*)d_in[4];
    const float* be1  = (const float*)d_in[5];
    const float* W2   = (const float*)d_in[6];
    const float* b2   = (const float*)d_in[7];
    const float* fW1  = (const float*)d_in[8];
    const float* fb1  = (const float*)d_in[9];
    const float* fg1  = (const float*)d_in[10];
    const float* fbe1 = (const float*)d_in[11];
    const float* fW2  = (const float*)d_in[12];
    const float* fb2  = (const float*)d_in[13];
    float* out = (float*)d_out;

    float *A, *C;
    uint32_t *hi, *lo, *wh, *wl;
    cudaGetSymbolAddress((void**)&A, g_bufA);
    cudaGetSymbolAddress((void**)&C, g_bufC);
    cudaGetSymbolAddress((void**)&hi, g_hi);
    cudaGetSymbolAddress((void**)&lo, g_lo);
    cudaGetSymbolAddress((void**)&wh, g_wh);
    cudaGetSymbolAddress((void**)&wl, g_wl);

    const int SMA = 128 * 68 * 4 * 2;   // 69632 B
    const int SMB = 64 * 68 * 4 * 2;    // 34816 B
    cudaFuncSetAttribute(mma_gemm<128, false, true, 0>,
                         cudaFuncAttributeMaxDynamicSharedMemorySize, SMA);
    cudaFuncSetAttribute(mma_gemm<128, true, false, 0>,
                         cudaFuncAttributeMaxDynamicSharedMemorySize, SMA);
    cudaFuncSetAttribute(mma_gemm<128, true, false, 1>,
                         cudaFuncAttributeMaxDynamicSharedMemorySize, SMA);
    cudaFuncSetAttribute(mma_gemm<64, false, false, 0>,
                         cudaFuncAttributeMaxDynamicSharedMemorySize, SMB);

    detect_kernel<<<1, 256>>>(ei);
    prep_w<<<dim3(64, 8), 256>>>(W1, W2, fW1, fW2);

    // CSR build
    zero_deg_kernel<<<SCANB, 256>>>();
    hist_kernel<<<NE / 256, 256>>>(ei);
    scan1_kernel<<<SCANB, 256>>>();
    scan2_kernel<<<1, 512>>>();
    scan3_kernel<<<SCANB, 256>>>();
    fill_kernel<<<NE / 256, 256>>>(ei);
    zero_stats_kernel<<<1, 256>>>();

    const int gblocks = (NN * 32 + 255) / 256;   // 12500
    const int cblocks = (NN * 32 + 255) / 256;

    const float* cur = x;
    for (int l = 0; l < 3; ++l) {
        gather_bf16_kernel<<<gblocks, 256>>>(cur, hi, lo);
        mma_gemm<128, false, true, 0><<<NBLK, 256, SMA>>>(
            hi, lo, wh + (size_t)l * D * 64, wl + (size_t)l * D * 64, b1 + l * D, C,
            nullptr, nullptr);
        finalize_stats_kernel<<<1, 128>>>(g1 + l * D, be1 + l * D);
        conv_split_bn_kernel<<<cblocks, 256>>>(C, hi, lo);
        if (l < 2) {
            mma_gemm<128, true, false, 0><<<NBLK, 256, SMA>>>(
                hi, lo, wh + (size_t)(3 + l) * D * 64, wl + (size_t)(3 + l) * D * 64,
                b2 + l * D, A, nullptr, nullptr);
            cur = A;
        } else {
            // layer-3 GEMM2: emit bf16 hi/lo directly (skips conv_split<false>)
            mma_gemm<128, true, false, 1><<<NBLK, 256, SMA>>>(
                hi, lo, wh + (size_t)(3 + l) * D * 64, wl + (size_t)(3 + l) * D * 64,
                b2 + l * D, nullptr, hi, lo);
        }
    }
    // final MLP (hi/lo already hold split of layer-3 output)
    mma_gemm<128, false, true, 0><<<NBLK, 256, SMA>>>(
        hi, lo, wh + (size_t)6 * D * 64, wl + (size_t)6 * D * 64, fb1, C, nullptr, nullptr);
    finalize_stats_kernel<<<1, 128>>>(fg1, fbe1);
    conv_split_bn_kernel<<<cblocks, 256>>>(C, hi, lo);
    mma_gemm<64, false, false, 0><<<NBLK, 256, SMB>>>(
        hi, lo, wh + (size_t)7 * D * 64, wl + (size_t)7 * D * 64, fb2, out, nullptr, nullptr);
}

// round 10
// speedup vs baseline: 1.0600x; 1.0010x over previous
#include <cuda_runtime.h>
#include <cuda_bf16.h>
#include <cstdint>

#define NN   100000
#define NE   1600000
#define D    128
#define DOUT 64
#define MT   128
#define NBLK ((NN + MT - 1) / MT)     // 782
#define SCANB ((NN + 255) / 256)      // 391

// ---------------- scratch ----------------
__device__ __align__(16) float g_bufA[NN * D];
__device__ __align__(16) float g_bufC[NN * D];
__device__ __align__(16) uint32_t g_hi[NN * (D / 2)];
__device__ __align__(16) uint32_t g_lo[NN * (D / 2)];
__device__ __align__(16) float g_stats2[4 * 256];  // per-stats-GEMM: [sum(128), sumsq(128)]
__device__ int g_is64;
__device__ int g_deg[NN];
__device__ int g_off[NN];
__device__ int g_cur[NN];
__device__ int g_csr[NE];
__device__ int g_bsum[512];
__device__ __align__(16) __nv_bfloat16 g_wh[8 * D * D];
__device__ __align__(16) __nv_bfloat16 g_wl[8 * D * D];

__device__ __forceinline__ uint32_t pack2(__nv_bfloat16 a, __nv_bfloat16 b) {
    return (uint32_t)__bfloat16_as_ushort(a) | ((uint32_t)__bfloat16_as_ushort(b) << 16);
}
__device__ __forceinline__ void split2(float x, float y, uint32_t& h, uint32_t& l) {
    __nv_bfloat16 hx = __float2bfloat16(x), hy = __float2bfloat16(y);
    h = pack2(hx, hy);
    l = pack2(__float2bfloat16(x - __bfloat162float(hx)),
              __float2bfloat16(y - __bfloat162float(hy)));
}

#define MMA_BF16(c, a, b0_, b1_) \
    asm volatile("mma.sync.aligned.m16n8k16.row.col.f32.bf16.bf16.f32 " \
        "{%0,%1,%2,%3}, {%4,%5,%6,%7}, {%8,%9}, {%0,%1,%2,%3};" \
        : "+f"((c)[0]), "+f"((c)[1]), "+f"((c)[2]), "+f"((c)[3]) \
        : "r"((a)[0]), "r"((a)[1]), "r"((a)[2]), "r"((a)[3]), "r"(b0_), "r"(b1_))

// ---------------- init: zero deg + detect dtype + zero stats slots ----------------
__global__ void init_kernel(const void* ei) {
    if (blockIdx.x < SCANB) {
        int i = blockIdx.x * 256 + threadIdx.x;
        if (i < NN) g_deg[i] = 0;
    } else {
        const long long* p = (const long long*)ei;
        long long v = p[threadIdx.x];
        int ok = (v >= 0 && v < NN);
        ok = __syncthreads_and(ok);
        if (threadIdx.x == 0) g_is64 = ok;
        ((float4*)g_stats2)[threadIdx.x] = make_float4(0.f, 0.f, 0.f, 0.f);
    }
}

// transpose + bf16-split all 8 weight matrices: g_wh/g_wl[m][n][k]
__global__ void prep_w(const float* __restrict__ W1, const float* __restrict__ W2,
                       const float* __restrict__ fW1, const float* __restrict__ fW2) {
    int m = blockIdx.y;
    const float* src;
    int ncols;
    if (m < 3)       { src = W1 + m * D * D;       ncols = D; }
    else if (m < 6)  { src = W2 + (m - 3) * D * D; ncols = D; }
    else if (m == 6) { src = fW1;                  ncols = D; }
    else             { src = fW2;                  ncols = DOUT; }
    int idx = blockIdx.x * 256 + threadIdx.x;
    if (idx >= ncols * D) return;
    int n = idx / D, k = idx % D;
    float v = __ldg(src + k * ncols + n);
    __nv_bfloat16 h = __float2bfloat16(v);
    g_wh[m * D * D + idx] = h;
    g_wl[m * D * D + idx] = __float2bfloat16(v - __bfloat162float(h));
}

__global__ void hist_kernel(const void* ei) {
    int e = blockIdx.x * 256 + threadIdx.x;
    if (e >= NE) return;
    int d = g_is64 ? (int)((const long long*)ei)[NE + e] : ((const int*)ei)[NE + e];
    atomicAdd(&g_deg[d], 1);
}
__global__ void scan1_kernel() {
    __shared__ int s[256];
    int i = blockIdx.x * 256 + threadIdx.x;
    int v = (i < NN) ? g_deg[i] : 0;
    s[threadIdx.x] = v;
    __syncthreads();
    for (int o = 1; o < 256; o <<= 1) {
        int t = (threadIdx.x >= o) ? s[threadIdx.x - o] : 0;
        __syncthreads();
        s[threadIdx.x] += t;
        __syncthreads();
    }
    if (i < NN) g_off[i] = s[threadIdx.x];
    if (threadIdx.x == 255) g_bsum[blockIdx.x] = s[255];
}
__global__ void scan2_kernel() {
    __shared__ int s[512];
    int v = (threadIdx.x < SCANB) ? g_bsum[threadIdx.x] : 0;
    s[threadIdx.x] = v;
    __syncthreads();
    for (int o = 1; o < 512; o <<= 1) {
        int t = (threadIdx.x >= o) ? s[threadIdx.x - o] : 0;
        __syncthreads();
        s[threadIdx.x] += t;
        __syncthreads();
    }
    g_bsum[threadIdx.x] = s[threadIdx.x] - v;
}
__global__ void scan3_kernel() {
    int i = blockIdx.x * 256 + threadIdx.x;
    if (i >= NN) return;
    int e = g_off[i] - g_deg[i] + g_bsum[blockIdx.x];
    g_off[i] = e;
    g_cur[i] = e;
}
__global__ void fill_kernel(const void* ei) {
    int e = blockIdx.x * 256 + threadIdx.x;
    if (e >= NE) return;
    int s, d;
    if (g_is64) { const long long* p = (const long long*)ei; s = (int)p[e]; d = (int)p[NE + e]; }
    else        { const int* p = (const int*)ei;             s = p[e];      d = p[NE + e]; }
    int pos = atomicAdd(&g_cur[d], 1);
    g_csr[pos] = s;
}

// gather h[w] = x[w] + sum_j x[csr[j]]  -> bf16 hi/lo split, one warp per node
__global__ __launch_bounds__(256)
void gather_bf16_kernel(const float* __restrict__ x,
                        uint32_t* __restrict__ hi, uint32_t* __restrict__ lo) {
    int w = (blockIdx.x * 256 + threadIdx.x) >> 5;
    int lane = threadIdx.x & 31;
    if (w >= NN) return;
    const float4* xb = (const float4*)x;
    float4 acc = __ldg(xb + (size_t)w * 32 + lane);
    int i = g_off[w];
    int end = i + g_deg[w];
    for (; i + 4 <= end; i += 4) {
        int s0 = __ldg(g_csr + i),     s1 = __ldg(g_csr + i + 1);
        int s2 = __ldg(g_csr + i + 2), s3 = __ldg(g_csr + i + 3);
        float4 v0 = __ldg(xb + (size_t)s0 * 32 + lane);
        float4 v1 = __ldg(xb + (size_t)s1 * 32 + lane);
        float4 v2 = __ldg(xb + (size_t)s2 * 32 + lane);
        float4 v3 = __ldg(xb + (size_t)s3 * 32 + lane);
        acc.x += (v0.x + v1.x) + (v2.x + v3.x);
        acc.y += (v0.y + v1.y) + (v2.y + v3.y);
        acc.z += (v0.z + v1.z) + (v2.z + v3.z);
        acc.w += (v0.w + v1.w) + (v2.w + v3.w);
    }
    for (; i < end; ++i) {
        int s = __ldg(g_csr + i);
        float4 v = __ldg(xb + (size_t)s * 32 + lane);
        acc.x += v.x; acc.y += v.y; acc.z += v.z; acc.w += v.w;
    }
    uint32_t h0, l0, h1, l1;
    split2(acc.x, acc.y, h0, l0);
    split2(acc.z, acc.w, h1, l1);
    ((uint2*)hi)[(size_t)w * 32 + lane] = make_uint2(h0, h1);
    ((uint2*)lo)[(size_t)w * 32 + lane] = make_uint2(l0, l1);
}

// conv: fp32 -> bf16 hi/lo with BN+ReLU; scale/shift computed per-BLOCK in smem
__global__ __launch_bounds__(256)
void conv_split_bn_kernel(const float* __restrict__ C,
                          uint32_t* __restrict__ hi, uint32_t* __restrict__ lo,
                          const float* __restrict__ stats,
                          const float* __restrict__ gamma,
                          const float* __restrict__ beta) {
    __shared__ float sc_s[128], sh_s[128];
    int tid = threadIdx.x;
    if (tid < 128) {
        float mu  = stats[tid] * (1.0f / NN);
        float var = stats[128 + tid] * (1.0f / NN) - mu * mu;
        float sc  = __ldg(gamma + tid) * rsqrtf(var + 1e-5f);
        sc_s[tid] = sc;
        sh_s[tid] = __ldg(beta + tid) - mu * sc;
    }
    __syncthreads();
    int i = blockIdx.x * 256 + tid;
    if (i >= NN * 32) return;
    float4 v = __ldg((const float4*)C + i);
    int k = (i & 31) * 4;
    float4 sc = *(const float4*)(sc_s + k);
    float4 sh = *(const float4*)(sh_s + k);
    v.x = fmaxf(fmaf(v.x, sc.x, sh.x), 0.f);
    v.y = fmaxf(fmaf(v.y, sc.y, sh.y), 0.f);
    v.z = fmaxf(fmaf(v.z, sc.z, sh.z), 0.f);
    v.w = fmaxf(fmaf(v.w, sc.w, sh.w), 0.f);
    uint32_t h0, l0, h1, l1;
    split2(v.x, v.y, h0, l0);
    split2(v.z, v.w, h1, l1);
    ((uint2*)hi)[i] = make_uint2(h0, h1);
    ((uint2*)lo)[i] = make_uint2(l0, l1);
}

// ---------------- HMMA GEMM: Out = split(A) @ Wt^T + bias ----------------
// STATS: fused column sum/sumsq of Out into stats[0:256) (shfl-reduced epilogue).
// EMIT:  0 = store fp32 Out; 1 = store bf16 hi/lo split (Ohi/Olo) instead.
template <int NOUT, bool RELU, bool STATS, int EMIT>
__global__ __launch_bounds__(256, 2)
void mma_gemm(const uint32_t* __restrict__ Ahi, const uint32_t* __restrict__ Alo,
              const uint32_t* __restrict__ Wh, const uint32_t* __restrict__ Wl,
              const float* __restrict__ bias, float* __restrict__ Out,
              uint32_t* __restrict__ Ohi, uint32_t* __restrict__ Olo,
              float* __restrict__ stats) {
    constexpr int WM = (NOUT == 128) ? 4 : 8;   // warps along m
    constexpr int MF = 128 / (WM * 16);         // m16 frags per warp
    constexpr int RS = 68;                      // smem row stride (u32), pad for banks
    extern __shared__ uint32_t ws[];
    uint32_t* wh_s = ws;
    uint32_t* wl_s = ws + NOUT * RS;
    __shared__ float ssum[128], ssq[128];

    int tid = threadIdx.x;
    for (int i = tid; i < NOUT * 64; i += 256) {
        int n = i >> 6, kw = i & 63;
        wh_s[n * RS + kw] = __ldg(Wh + i);
        wl_s[n * RS + kw] = __ldg(Wl + i);
    }
    if (STATS && tid < 128) { ssum[tid] = 0.f; ssq[tid] = 0.f; }
    __syncthreads();

    int wid = tid >> 5, lane = tid & 31;
    int g = lane >> 2, tig = lane & 3;
    int mwid = wid % WM, nwid = wid / WM;
    int n0 = nwid * 64;
    int mbase = blockIdx.x * MT + mwid * (MF * 16);

    float acc[MF][8][4];
#pragma unroll
    for (int mf = 0; mf < MF; ++mf)
#pragma unroll
        for (int nf = 0; nf < 8; ++nf)
#pragma unroll
            for (int c = 0; c < 4; ++c) acc[mf][nf][c] = 0.f;

    for (int ks = 0; ks < 8; ++ks) {
        uint32_t ah[MF][4], al[MF][4];
#pragma unroll
        for (int mf = 0; mf < MF; ++mf) {
            int r0 = mbase + mf * 16 + g;
            int r1 = r0 + 8;
            int o = ks * 8 + tig;
            bool v0 = r0 < NN, v1 = r1 < NN;
            size_t p0 = (size_t)r0 * 64 + o, p1 = (size_t)r1 * 64 + o;
            ah[mf][0] = v0 ? __ldg(Ahi + p0) : 0u;
            ah[mf][1] = v1 ? __ldg(Ahi + p1) : 0u;
            ah[mf][2] = v0 ? __ldg(Ahi + p0 + 4) : 0u;
            ah[mf][3] = v1 ? __ldg(Ahi + p1 + 4) : 0u;
            al[mf][0] = v0 ? __ldg(Alo + p0) : 0u;
            al[mf][1] = v1 ? __ldg(Alo + p1) : 0u;
            al[mf][2] = v0 ? __ldg(Alo + p0 + 4) : 0u;
            al[mf][3] = v1 ? __ldg(Alo + p1 + 4) : 0u;
        }
#pragma unroll
        for (int nf = 0; nf < 8; ++nf) {
            int bo = (n0 + nf * 8 + g) * RS + ks * 8 + tig;
            uint32_t bh0 = wh_s[bo], bh1 = wh_s[bo + 4];
            uint32_t bl0 = wl_s[bo], bl1 = wl_s[bo + 4];
#pragma unroll
            for (int mf = 0; mf < MF; ++mf) {
                MMA_BF16(acc[mf][nf], ah[mf], bh0, bh1);
                MMA_BF16(acc[mf][nf], al[mf], bh0, bh1);
                MMA_BF16(acc[mf][nf], ah[mf], bl0, bl1);
            }
        }
    }

#pragma unroll
    for (int nf = 0; nf < 8; ++nf) {
        int col = n0 + nf * 8 + tig * 2;
        float2 b = *(const float2*)(bias + col);
        float s0 = 0.f, s1 = 0.f, q0 = 0.f, q1 = 0.f;
#pragma unroll
        for (int mf = 0; mf < MF; ++mf) {
            int r0 = mbase + mf * 16 + g;
            int r1 = r0 + 8;
            float c0 = acc[mf][nf][0] + b.x, c1 = acc[mf][nf][1] + b.y;
            float c2 = acc[mf][nf][2] + b.x, c3 = acc[mf][nf][3] + b.y;
            if (RELU) {
                c0 = fmaxf(c0, 0.f); c1 = fmaxf(c1, 0.f);
                c2 = fmaxf(c2, 0.f); c3 = fmaxf(c3, 0.f);
            }
            if (r0 < NN) {
                if (EMIT) {
                    uint32_t hh, ll;
                    split2(c0, c1, hh, ll);
                    Ohi[(size_t)r0 * 64 + col / 2] = hh;
                    Olo[(size_t)r0 * 64 + col / 2] = ll;
                } else {
                    *(float2*)(Out + (size_t)r0 * NOUT + col) = make_float2(c0, c1);
                }
                if (STATS) { s0 += c0; s1 += c1; q0 += c0 * c0; q1 += c1 * c1; }
            }
            if (r1 < NN) {
                if (EMIT) {
                    uint32_t hh, ll;
                    split2(c2, c3, hh, ll);
                    Ohi[(size_t)r1 * 64 + col / 2] = hh;
                    Olo[(size_t)r1 * 64 + col / 2] = ll;
                } else {
                    *(float2*)(Out + (size_t)r1 * NOUT + col) = make_float2(c2, c3);
                }
                if (STATS) { s0 += c2; s1 += c3; q0 += c2 * c2; q1 += c3 * c3; }
            }
        }
        if (STATS) {
#pragma unroll
            for (int o = 4; o < 32; o <<= 1) {
                s0 += __shfl_xor_sync(0xFFFFFFFFu, s0, o);
                s1 += __shfl_xor_sync(0xFFFFFFFFu, s1, o);
                q0 += __shfl_xor_sync(0xFFFFFFFFu, q0, o);
                q1 += __shfl_xor_sync(0xFFFFFFFFu, q1, o);
            }
            if (lane < 4) {
                atomicAdd(&ssum[col], s0);
                atomicAdd(&ssum[col + 1], s1);
                atomicAdd(&ssq[col], q0);
                atomicAdd(&ssq[col + 1], q1);
            }
        }
    }
    if (STATS) {
        __syncthreads();
        if (tid < 128) {
            atomicAdd(&stats[tid], ssum[tid]);
            atomicAdd(&stats[128 + tid], ssq[tid]);
        }
    }
}

// ---------------- host ----------------
extern "C" void kernel_launch(void* const* d_in, const int* in_sizes, int n_in,
                              void* d_out, int out_size) {
    const float* x    = (const float*)d_in[0];
    const void*  ei   = d_in[1];
    const float* W1   = (const float*)d_in[2];
    const float* b1   = (const float*)d_in[3];
    const float* g1   = (const float*)d_in[4];
    const float* be1  = (const float*)d_in[5];
    const float* W2   = (const float*)d_in[6];
    const float* b2   = (const float*)d_in[7];
    const float* fW1  = (const float*)d_in[8];
    const float* fb1  = (const float*)d_in[9];
    const float* fg1  = (const float*)d_in[10];
    const float* fbe1 = (const float*)d_in[11];
    const float* fW2  = (const float*)d_in[12];
    const float* fb2  = (const float*)d_in[13];
    float* out = (float*)d_out;

    float *A, *C, *st;
    uint32_t *hi, *lo, *wh, *wl;
    cudaGetSymbolAddress((void**)&A, g_bufA);
    cudaGetSymbolAddress((void**)&C, g_bufC);
    cudaGetSymbolAddress((void**)&st, g_stats2);
    cudaGetSymbolAddress((void**)&hi, g_hi);
    cudaGetSymbolAddress((void**)&lo, g_lo);
    cudaGetSymbolAddress((void**)&wh, g_wh);
    cudaGetSymbolAddress((void**)&wl, g_wl);

    const int SMA = 128 * 68 * 4 * 2;   // 69632 B
    const int SMB = 64 * 68 * 4 * 2;    // 34816 B
    cudaFuncSetAttribute(mma_gemm<128, false, true, 0>,
                         cudaFuncAttributeMaxDynamicSharedMemorySize, SMA);
    cudaFuncSetAttribute(mma_gemm<128, true, false, 0>,
                         cudaFuncAttributeMaxDynamicSharedMemorySize, SMA);
    cudaFuncSetAttribute(mma_gemm<128, true, false, 1>,
                         cudaFuncAttributeMaxDynamicSharedMemorySize, SMA);
    cudaFuncSetAttribute(mma_gemm<64, false, false, 0>,
                         cudaFuncAttributeMaxDynamicSharedMemorySize, SMB);

    init_kernel<<<SCANB + 1, 256>>>(ei);
    prep_w<<<dim3(64, 8), 256>>>(W1, W2, fW1, fW2);
    hist_kernel<<<NE / 256, 256>>>(ei);
    scan1_kernel<<<SCANB, 256>>>();
    scan2_kernel<<<1, 512>>>();
    scan3_kernel<<<SCANB, 256>>>();
    fill_kernel<<<NE / 256, 256>>>(ei);

    const int gblocks = (NN * 32 + 255) / 256;   // 12500
    const int cblocks = (NN * 32 + 255) / 256;

    const float* cur = x;
    for (int l = 0; l < 3; ++l) {
        float* slot = st + l * 256;
        gather_bf16_kernel<<<gblocks, 256>>>(cur, hi, lo);
        mma_gemm<128, false, true, 0><<<NBLK, 256, SMA>>>(
            hi, lo, wh + (size_t)l * D * 64, wl + (size_t)l * D * 64, b1 + l * D, C,
            nullptr, nullptr, slot);
        conv_split_bn_kernel<<<cblocks, 256>>>(C, hi, lo, slot, g1 + l * D, be1 + l * D);
        if (l < 2) {
            mma_gemm<128, true, false, 0><<<NBLK, 256, SMA>>>(
                hi, lo, wh + (size_t)(3 + l) * D * 64, wl + (size_t)(3 + l) * D * 64,
                b2 + l * D, A, nullptr, nullptr, nullptr);
            cur = A;
        } else {
            // layer-3 GEMM2: emit bf16 hi/lo directly (in-place safe: block-local rows)
            mma_gemm<128, true, false, 1><<<NBLK, 256, SMA>>>(
                hi, lo, wh + (size_t)(3 + l) * D * 64, wl + (size_t)(3 + l) * D * 64,
                b2 + l * D, nullptr, hi, lo, nullptr);
        }
    }
    // final MLP
    mma_gemm<128, false, true, 0><<<NBLK, 256, SMA>>>(
        hi, lo, wh + (size_t)6 * D * 64, wl + (size_t)6 * D * 64, fb1, C,
        nullptr, nullptr, st + 3 * 256);
    conv_split_bn_kernel<<<cblocks, 256>>>(C, hi, lo, st + 3 * 256, fg1, fbe1);
    mma_gemm<64, false, false, 0><<<NBLK, 256, SMB>>>(
        hi, lo, wh + (size_t)7 * D * 64, wl + (size_t)7 * D * 64, fb2, out,
        nullptr, nullptr, nullptr);
}